// round 5
// baseline (speedup 1.0000x reference)
#include <cuda_runtime.h>
#include <cstdint>

// Shapes (fixed for this problem)
#define B_SZ   8
#define S_LEN  2048
#define E_SZ   128
#define NH     8
#define HS     16
#define ROWS_TOTAL (B_SZ * S_LEN)          // 16384

// softmax in base-2: fold scale = sqrt(hs)*log2(e) into Q
#define QSCALE 5.7707801635558535f          // 4 * log2(e)

// -------- scratch (device globals; no allocation allowed) --------
__device__ float g_q[B_SZ * NH * S_LEN * HS];     // [b,h,s,d]  (pre-scaled by QSCALE)
__device__ float g_k[B_SZ * NH * S_LEN * HS];
__device__ float g_v[B_SZ * NH * S_LEN * HS];
__device__ float g_ocat[ROWS_TOTAL * E_SZ];       // [b*s, h*hs]

// ================= helpers =================
__device__ __forceinline__ float ex2f(float x) {
    float y; asm("ex2.approx.ftz.f32 %0, %1;" : "=f"(y) : "f"(x)); return y;
}
__device__ __forceinline__ uint32_t smem_to_u32(const void* p) {
    uint32_t a;
    asm("{ .reg .u64 t; cvta.to.shared.u64 t, %1; cvt.u32.u64 %0, t; }" : "=r"(a) : "l"(p));
    return a;
}
// pack: lower 16 bits = bf16(a), upper = bf16(b)
#define CVT_BF16X2_F32(result, a, b) \
    asm("cvt.rn.satfinite.bf16x2.f32 %0, %1, %2;" : "=r"(result) : "f"(b), "f"(a))

// split fp32 pair -> (bf16x2 hi, bf16x2 lo)
__device__ __forceinline__ void split_pair(float a, float c, uint32_t& hi, uint32_t& lo) {
    CVT_BF16X2_F32(hi, a, c);
    float ar = a - __uint_as_float(hi << 16);
    float cr = c - __uint_as_float(hi & 0xffff0000u);
    CVT_BF16X2_F32(lo, ar, cr);
}

__device__ __forceinline__ void mma16816(float* c, const uint32_t* a, uint32_t b0, uint32_t b1) {
    asm volatile("mma.sync.aligned.m16n8k16.row.col.f32.bf16.bf16.f32 "
        "{%0,%1,%2,%3}, {%4,%5,%6,%7}, {%8,%9}, {%0,%1,%2,%3};"
        : "+f"(c[0]), "+f"(c[1]), "+f"(c[2]), "+f"(c[3])
        : "r"(a[0]), "r"(a[1]), "r"(a[2]), "r"(a[3]), "r"(b0), "r"(b1));
}
__device__ __forceinline__ void ldsm_x2(uint32_t& r0, uint32_t& r1, uint32_t addr) {
    asm volatile("ldmatrix.sync.aligned.m8n8.x2.shared.b16 {%0,%1}, [%2];"
        : "=r"(r0), "=r"(r1) : "r"(addr));
}
__device__ __forceinline__ void ldsm_x2_t(uint32_t& r0, uint32_t& r1, uint32_t addr) {
    asm volatile("ldmatrix.sync.aligned.m8n8.x2.trans.shared.b16 {%0,%1}, [%2];"
        : "=r"(r0), "=r"(r1) : "r"(addr));
}
__device__ __forceinline__ void ldsm_x4(uint32_t& r0, uint32_t& r1, uint32_t& r2, uint32_t& r3,
                                        uint32_t addr) {
    asm volatile("ldmatrix.sync.aligned.m8n8.x4.shared.b16 {%0,%1,%2,%3}, [%4];"
        : "=r"(r0), "=r"(r1), "=r"(r2), "=r"(r3) : "r"(addr));
}

// ======== shared GEMM config: C[rows,128] = X[rows,128] @ W^T, split bf16 ========
// smem W layout: row stride 136 halves (272B) -> ldmatrix conflict-free
#define WROW 136
#define SWHALF (128 * WROW)                 // halves per split
#define SWBYTES (2 * SWHALF * 2)            // 69632 bytes (hi + lo)

// load + split W[128x128] (row-major, k contiguous) into sWh/sWl
__device__ __forceinline__ void load_w_split(const float* __restrict__ W,
                                             uint16_t* sWh, uint16_t* sWl, int tid) {
    const int c  = tid >> 1;
    const int hf = tid & 1;
    const float4* wr4 = (const float4*)(W + c * 128 + hf * 64);
    uint16_t* dh = sWh + c * WROW + hf * 64;
    uint16_t* dl = sWl + c * WROW + hf * 64;
    #pragma unroll
    for (int i = 0; i < 16; i++) {
        float4 f = wr4[i];
        uint32_t h0, l0, h1, l1;
        split_pair(f.x, f.y, h0, l0);
        split_pair(f.z, f.w, h1, l1);
        *(uint2*)(dh + i * 4) = make_uint2(h0, h1);
        *(uint2*)(dl + i * 4) = make_uint2(l0, l1);
    }
}

// per-warp split-bf16 GEMM: 16 rows x 64 cols, K=128. acc[8][4] row-frag layout.
__device__ __forceinline__ void gemm_warp(const float* __restrict__ Xw,  // row0 of this warp
                                          uint32_t bh_base, uint32_t bl_base,
                                          int warp_n, uint32_t ld_off,
                                          int g, int t, float acc[8][4]) {
    #pragma unroll
    for (int i = 0; i < 8; i++)
        #pragma unroll
        for (int j = 0; j < 4; j++) acc[i][j] = 0.f;

    #pragma unroll
    for (int kc = 0; kc < 8; kc++) {
        const float* xr = Xw + g * 128 + kc * 16 + 2 * t;
        float2 a0 = *(const float2*)xr;
        float2 a1 = *(const float2*)(xr + 8 * 128);
        float2 a2 = *(const float2*)(xr + 8);
        float2 a3 = *(const float2*)(xr + 8 * 128 + 8);
        uint32_t ah[4], al[4];
        split_pair(a0.x, a0.y, ah[0], al[0]);
        split_pair(a1.x, a1.y, ah[1], al[1]);
        split_pair(a2.x, a2.y, ah[2], al[2]);
        split_pair(a3.x, a3.y, ah[3], al[3]);

        #pragma unroll
        for (int np = 0; np < 4; np++) {
            uint32_t roff = (uint32_t)((warp_n * 64 + np * 16) * 272 + kc * 32) + ld_off;
            uint32_t bh0, bh1, bh2, bh3, bl0, bl1, bl2, bl3;
            ldsm_x4(bh0, bh1, bh2, bh3, bh_base + roff);
            ldsm_x4(bl0, bl1, bl2, bl3, bl_base + roff);
            mma16816(acc[2*np],   ah, bh0, bh1);
            mma16816(acc[2*np],   al, bh0, bh1);
            mma16816(acc[2*np],   ah, bl0, bl1);
            mma16816(acc[2*np+1], ah, bh2, bh3);
            mma16816(acc[2*np+1], al, bh2, bh3);
            mma16816(acc[2*np+1], ah, bl2, bl3);
        }
    }
}

// ============================================================
// Kernel 1: fused QKV projection via HMMA (Q pre-scaled)
// CTA: 64 rows x 128 cols; 8 warps (4m x 2n); 3 weight passes.
// ============================================================
__global__ __launch_bounds__(256) void qkv_mma_kernel(
    const float* __restrict__ x,
    const float* __restrict__ Wq,
    const float* __restrict__ Wk,
    const float* __restrict__ Wv)
{
    extern __shared__ __align__(16) uint16_t sw[];
    uint16_t* sWh = sw;
    uint16_t* sWl = sw + SWHALF;

    const int tid  = threadIdx.x;
    const int warp = tid >> 5;
    const int lane = tid & 31;
    const int g = lane >> 2;
    const int t = lane & 3;
    const int warp_m = warp >> 1;
    const int warp_n = warp & 1;
    const int row_cta = blockIdx.x * 64;

    const uint32_t bh_base = smem_to_u32(sWh);
    const uint32_t bl_base = smem_to_u32(sWl);
    const uint32_t ld_off = (uint32_t)(((lane & 7) + ((lane >> 4) & 1) * 8) * 272
                                       + ((lane >> 3) & 1) * 16);

    const float* Xw = x + (size_t)(row_cta + warp_m * 16) * 128;

    const float* Wmats[3] = {Wq, Wk, Wv};
    float*       Omats[3] = {g_q, g_k, g_v};

    const int rT = row_cta + warp_m * 16 + g;     // same b for whole CTA (64 | 2048)
    const int b = rT >> 11;
    const int sT = rT & 2047;

    for (int mtx = 0; mtx < 3; mtx++) {
        load_w_split(Wmats[mtx], sWh, sWl, tid);
        __syncthreads();

        float acc[8][4];
        gemm_warp(Xw, bh_base, bl_base, warp_n, ld_off, g, t, acc);

        const float scl = (mtx == 0) ? QSCALE : 1.0f;
        float* OP = Omats[mtx];
        #pragma unroll
        for (int nt = 0; nt < 8; nt++) {
            int col = warp_n * 64 + nt * 8 + 2 * t;
            int h = col >> 4;
            int d = col & 15;
            float* pT = OP + ((size_t)(b * NH + h) * S_LEN + sT) * HS + d;
            *(float2*)pT       = make_float2(acc[nt][0] * scl, acc[nt][1] * scl);
            *(float2*)(pT + 8 * HS) = make_float2(acc[nt][2] * scl, acc[nt][3] * scl);
        }
        __syncthreads();
    }
}

// ============================================================
// Kernel 2: FA2-style HMMA flash attention (unchanged from R3).
// ============================================================
__global__ __launch_bounds__(128) void att_mma_kernel()
{
    __shared__ __align__(16) uint16_t sKh[64 * 24];
    __shared__ __align__(16) uint16_t sKl[64 * 24];
    __shared__ __align__(16) uint16_t sVh[64 * 24];
    __shared__ __align__(16) uint16_t sVl[64 * 24];

    const int tid  = threadIdx.x;
    const int warp = tid >> 5;
    const int lane = tid & 31;
    const int g = lane >> 2;
    const int t = lane & 3;
    const int bid = blockIdx.x;
    const int qt = bid & 15;
    const int h  = (bid >> 4) & 7;
    const int b  = bid >> 7;
    const int bh = b * NH + h;
    const int qbase = qt * 128 + warp * 32;

    uint32_t qh[2][4], ql[2][4];
    {
        const float* Qg = g_q + (size_t)bh * S_LEN * HS;
        #pragma unroll
        for (int mt = 0; mt < 2; mt++) {
            int rA = qbase + mt * 16 + g;
            int rB = rA + 8;
            float2 a0 = *(const float2*)(Qg + rA * HS + 2 * t);
            float2 a1 = *(const float2*)(Qg + rB * HS + 2 * t);
            float2 a2 = *(const float2*)(Qg + rA * HS + 2 * t + 8);
            float2 a3 = *(const float2*)(Qg + rB * HS + 2 * t + 8);
            split_pair(a0.x, a0.y, qh[mt][0], ql[mt][0]);
            split_pair(a1.x, a1.y, qh[mt][1], ql[mt][1]);
            split_pair(a2.x, a2.y, qh[mt][2], ql[mt][2]);
            split_pair(a3.x, a3.y, qh[mt][3], ql[mt][3]);
        }
    }

    float o[2][2][4];
    #pragma unroll
    for (int mt = 0; mt < 2; mt++)
        #pragma unroll
        for (int nO = 0; nO < 2; nO++)
            #pragma unroll
            for (int j = 0; j < 4; j++) o[mt][nO][j] = 0.f;
    float m[4] = {-1e30f, -1e30f, -1e30f, -1e30f};
    float l[4] = {0.f, 0.f, 0.f, 0.f};

    const uint32_t kh_b = smem_to_u32(sKh), kl_b = smem_to_u32(sKl);
    const uint32_t vh_b = smem_to_u32(sVh), vl_b = smem_to_u32(sVl);
    const int l15 = lane & 15;
    const uint32_t k_off = (uint32_t)((lane & 7) * 48 + ((l15 >> 3) << 4));
    const uint32_t v_off = (uint32_t)(l15 * 48);

    const int r  = tid >> 1;
    const int hf = tid & 1;
    const float* Ksrc0 = g_k + ((size_t)bh * S_LEN + r) * HS + hf * 8;
    const float* Vsrc0 = g_v + ((size_t)bh * S_LEN + r) * HS + hf * 8;
    char* kh_st = (char*)sKh + r * 48 + hf * 16;
    char* kl_st = (char*)sKl + r * 48 + hf * 16;
    char* vh_st = (char*)sVh + r * 48 + hf * 16;
    char* vl_st = (char*)sVl + r * 48 + hf * 16;

    for (int kt = 0; kt < S_LEN / 64; kt++) {
        __syncthreads();
        {
            const float* Ks = Ksrc0 + (size_t)kt * 64 * HS;
            float4 f0 = *(const float4*)Ks;
            float4 f1 = *(const float4*)(Ks + 4);
            uint32_t h0,h1,h2,h3, L0,L1,L2,L3;
            split_pair(f0.x, f0.y, h0, L0); split_pair(f0.z, f0.w, h1, L1);
            split_pair(f1.x, f1.y, h2, L2); split_pair(f1.z, f1.w, h3, L3);
            *(uint4*)kh_st = make_uint4(h0, h1, h2, h3);
            *(uint4*)kl_st = make_uint4(L0, L1, L2, L3);

            const float* Vs = Vsrc0 + (size_t)kt * 64 * HS;
            float4 g0 = *(const float4*)Vs;
            float4 g1 = *(const float4*)(Vs + 4);
            split_pair(g0.x, g0.y, h0, L0); split_pair(g0.z, g0.w, h1, L1);
            split_pair(g1.x, g1.y, h2, L2); split_pair(g1.z, g1.w, h3, L3);
            *(uint4*)vh_st = make_uint4(h0, h1, h2, h3);
            *(uint4*)vl_st = make_uint4(L0, L1, L2, L3);
        }
        __syncthreads();

        float sc[2][8][4];
        #pragma unroll
        for (int mt = 0; mt < 2; mt++)
            #pragma unroll
            for (int n = 0; n < 8; n++)
                #pragma unroll
                for (int j = 0; j < 4; j++) sc[mt][n][j] = 0.f;

        #pragma unroll
        for (int n = 0; n < 8; n++) {
            uint32_t kh0, kh1, kl0, kl1;
            ldsm_x2(kh0, kh1, kh_b + n * (8 * 48) + k_off);
            ldsm_x2(kl0, kl1, kl_b + n * (8 * 48) + k_off);
            #pragma unroll
            for (int mt = 0; mt < 2; mt++) {
                mma16816(sc[mt][n], qh[mt], kh0, kh1);
                mma16816(sc[mt][n], ql[mt], kh0, kh1);
                mma16816(sc[mt][n], qh[mt], kl0, kl1);
            }
        }

        #pragma unroll
        for (int mt = 0; mt < 2; mt++) {
            float mxt = -1e30f, mxb = -1e30f;
            #pragma unroll
            for (int n = 0; n < 8; n++) {
                mxt = fmaxf(mxt, fmaxf(sc[mt][n][0], sc[mt][n][1]));
                mxb = fmaxf(mxb, fmaxf(sc[mt][n][2], sc[mt][n][3]));
            }
            mxt = fmaxf(mxt, __shfl_xor_sync(0xffffffffu, mxt, 1));
            mxt = fmaxf(mxt, __shfl_xor_sync(0xffffffffu, mxt, 2));
            mxb = fmaxf(mxb, __shfl_xor_sync(0xffffffffu, mxb, 1));
            mxb = fmaxf(mxb, __shfl_xor_sync(0xffffffffu, mxb, 2));

            const int st = mt * 2, sbo = mt * 2 + 1;
            float mnt = fmaxf(m[st],  mxt);
            float mnb = fmaxf(m[sbo], mxb);
            float ct = ex2f(m[st]  - mnt);
            float cb = ex2f(m[sbo] - mnb);
            m[st] = mnt; m[sbo] = mnb;
            l[st] *= ct; l[sbo] *= cb;
            #pragma unroll
            for (int nO = 0; nO < 2; nO++) {
                o[mt][nO][0] *= ct; o[mt][nO][1] *= ct;
                o[mt][nO][2] *= cb; o[mt][nO][3] *= cb;
            }
            float lt = 0.f, lb = 0.f;
            #pragma unroll
            for (int n = 0; n < 8; n++) {
                sc[mt][n][0] = ex2f(sc[mt][n][0] - mnt);
                sc[mt][n][1] = ex2f(sc[mt][n][1] - mnt);
                sc[mt][n][2] = ex2f(sc[mt][n][2] - mnb);
                sc[mt][n][3] = ex2f(sc[mt][n][3] - mnb);
                lt += sc[mt][n][0] + sc[mt][n][1];
                lb += sc[mt][n][2] + sc[mt][n][3];
            }
            l[st] += lt; l[sbo] += lb;
        }

        #pragma unroll
        for (int ks = 0; ks < 4; ks++) {
            uint32_t pa[2][4];
            #pragma unroll
            for (int mt = 0; mt < 2; mt++) {
                CVT_BF16X2_F32(pa[mt][0], sc[mt][2*ks  ][0], sc[mt][2*ks  ][1]);
                CVT_BF16X2_F32(pa[mt][1], sc[mt][2*ks  ][2], sc[mt][2*ks  ][3]);
                CVT_BF16X2_F32(pa[mt][2], sc[mt][2*ks+1][0], sc[mt][2*ks+1][1]);
                CVT_BF16X2_F32(pa[mt][3], sc[mt][2*ks+1][2], sc[mt][2*ks+1][3]);
            }
            #pragma unroll
            for (int nO = 0; nO < 2; nO++) {
                uint32_t vh0, vh1, vl0, vl1;
                ldsm_x2_t(vh0, vh1, vh_b + ks * (16 * 48) + v_off + nO * 16);
                ldsm_x2_t(vl0, vl1, vl_b + ks * (16 * 48) + v_off + nO * 16);
                mma16816(o[0][nO], pa[0], vh0, vh1);
                mma16816(o[0][nO], pa[0], vl0, vl1);
                mma16816(o[1][nO], pa[1], vh0, vh1);
                mma16816(o[1][nO], pa[1], vl0, vl1);
            }
        }
    }

    #pragma unroll
    for (int s = 0; s < 4; s++) {
        l[s] += __shfl_xor_sync(0xffffffffu, l[s], 1);
        l[s] += __shfl_xor_sync(0xffffffffu, l[s], 2);
    }
    #pragma unroll
    for (int mt = 0; mt < 2; mt++) {
        int rT = qbase + mt * 16 + g;
        int rB = rT + 8;
        float iT = 1.0f / l[mt * 2];
        float iB = 1.0f / l[mt * 2 + 1];
        #pragma unroll
        for (int nO = 0; nO < 2; nO++) {
            float* pT = g_ocat + ((size_t)b * S_LEN + rT) * E_SZ + h * HS + nO * 8 + 2 * t;
            float* pB = g_ocat + ((size_t)b * S_LEN + rB) * E_SZ + h * HS + nO * 8 + 2 * t;
            *(float2*)pT = make_float2(o[mt][nO][0] * iT, o[mt][nO][1] * iT);
            *(float2*)pB = make_float2(o[mt][nO][2] * iB, o[mt][nO][3] * iB);
        }
    }
}

// ============================================================
// Kernel 3: output projection via HMMA  out = ocat @ Wp^T + bp
// ============================================================
__global__ __launch_bounds__(256) void proj_mma_kernel(
    const float* __restrict__ Wp,
    const float* __restrict__ bp,
    float* __restrict__ out)
{
    extern __shared__ __align__(16) uint16_t sw[];
    uint16_t* sWh = sw;
    uint16_t* sWl = sw + SWHALF;

    const int tid  = threadIdx.x;
    const int warp = tid >> 5;
    const int lane = tid & 31;
    const int g = lane >> 2;
    const int t = lane & 3;
    const int warp_m = warp >> 1;
    const int warp_n = warp & 1;
    const int row_cta = blockIdx.x * 64;

    const uint32_t bh_base = smem_to_u32(sWh);
    const uint32_t bl_base = smem_to_u32(sWl);
    const uint32_t ld_off = (uint32_t)(((lane & 7) + ((lane >> 4) & 1) * 8) * 272
                                       + ((lane >> 3) & 1) * 16);

    load_w_split(Wp, sWh, sWl, tid);
    __syncthreads();

    const float* Xw = g_ocat + (size_t)(row_cta + warp_m * 16) * 128;
    float acc[8][4];
    gemm_warp(Xw, bh_base, bl_base, warp_n, ld_off, g, t, acc);

    const int rT = row_cta + warp_m * 16 + g;
    #pragma unroll
    for (int nt = 0; nt < 8; nt++) {
        int col = warp_n * 64 + nt * 8 + 2 * t;
        float2 bias = *(const float2*)(bp + col);
        float* pT = out + (size_t)rT * 128 + col;
        *(float2*)pT = make_float2(acc[nt][0] + bias.x, acc[nt][1] + bias.y);
        *(float2*)(pT + 8 * 128) = make_float2(acc[nt][2] + bias.x, acc[nt][3] + bias.y);
    }
}

// ============================================================
// launch: inputs are (x, Wk, Wq, Wv, Wp, bp) per metadata order
// ============================================================
extern "C" void kernel_launch(void* const* d_in, const int* in_sizes, int n_in,
                              void* d_out, int out_size)
{
    const float* x  = (const float*)d_in[0];
    const float* Wk = (const float*)d_in[1];
    const float* Wq = (const float*)d_in[2];
    const float* Wv = (const float*)d_in[3];
    const float* Wp = (const float*)d_in[4];
    const float* bp = (const float*)d_in[5];
    float* out = (float*)d_out;

    static bool attr_done = false;
    if (!attr_done) {
        cudaFuncSetAttribute(qkv_mma_kernel,  cudaFuncAttributeMaxDynamicSharedMemorySize, SWBYTES);
        cudaFuncSetAttribute(proj_mma_kernel, cudaFuncAttributeMaxDynamicSharedMemorySize, SWBYTES);
        attr_done = true;
    }

    qkv_mma_kernel<<<ROWS_TOTAL / 64, 256, SWBYTES>>>(x, Wq, Wk, Wv);
    att_mma_kernel<<<B_SZ * NH * (S_LEN / 128), 128>>>();
    proj_mma_kernel<<<ROWS_TOTAL / 64, 256, SWBYTES>>>(Wp, bp, out);
}

// round 7
// speedup vs baseline: 1.4112x; 1.4112x over previous
#include <cuda_runtime.h>
#include <cstdint>

// Shapes (fixed for this problem)
#define B_SZ   8
#define S_LEN  2048
#define E_SZ   128
#define NH     8
#define HS     16
#define ROWS_TOTAL (B_SZ * S_LEN)          // 16384

// softmax in base-2: fold scale = sqrt(hs)*log2(e) into Q
#define QSCALE 5.7707801635558535f          // 4 * log2(e)

// -------- scratch (device globals; no allocation allowed) --------
__device__ float g_q[B_SZ * NH * S_LEN * HS];              // [b,h,s,d] (pre-scaled)
__device__ float g_ocat[ROWS_TOTAL * E_SZ];                // [b*s, h*hs]
// W images: 4 matrices x (hi 34816B + lo 34816B), 136-half row stride
__device__ __align__(16) char g_wimg[4 * 69632];
// K/V tile images: [bh][tile] x 12288B block = Kh(64x24h) | Kl | Vh | Vl
__device__ __align__(16) char g_kvimg[B_SZ * NH * 32 * 12288];

// ================= helpers =================
__device__ __forceinline__ float ex2f(float x) {
    float y; asm("ex2.approx.ftz.f32 %0, %1;" : "=f"(y) : "f"(x)); return y;
}
__device__ __forceinline__ uint32_t smem_to_u32(const void* p) {
    uint32_t a;
    asm("{ .reg .u64 t; cvta.to.shared.u64 t, %1; cvt.u32.u64 %0, t; }" : "=r"(a) : "l"(p));
    return a;
}
#define CVT_BF16X2_F32(result, a, b) \
    asm("cvt.rn.satfinite.bf16x2.f32 %0, %1, %2;" : "=r"(result) : "f"(b), "f"(a))

__device__ __forceinline__ void split_pair(float a, float c, uint32_t& hi, uint32_t& lo) {
    CVT_BF16X2_F32(hi, a, c);
    float ar = a - __uint_as_float(hi << 16);
    float cr = c - __uint_as_float(hi & 0xffff0000u);
    CVT_BF16X2_F32(lo, ar, cr);
}

__device__ __forceinline__ void mma16816(float* c, const uint32_t* a, uint32_t b0, uint32_t b1) {
    asm volatile("mma.sync.aligned.m16n8k16.row.col.f32.bf16.bf16.f32 "
        "{%0,%1,%2,%3}, {%4,%5,%6,%7}, {%8,%9}, {%0,%1,%2,%3};"
        : "+f"(c[0]), "+f"(c[1]), "+f"(c[2]), "+f"(c[3])
        : "r"(a[0]), "r"(a[1]), "r"(a[2]), "r"(a[3]), "r"(b0), "r"(b1));
}
__device__ __forceinline__ void ldsm_x2(uint32_t& r0, uint32_t& r1, uint32_t addr) {
    asm volatile("ldmatrix.sync.aligned.m8n8.x2.shared.b16 {%0,%1}, [%2];"
        : "=r"(r0), "=r"(r1) : "r"(addr));
}
__device__ __forceinline__ void ldsm_x2_t(uint32_t& r0, uint32_t& r1, uint32_t addr) {
    asm volatile("ldmatrix.sync.aligned.m8n8.x2.trans.shared.b16 {%0,%1}, [%2];"
        : "=r"(r0), "=r"(r1) : "r"(addr));
}
__device__ __forceinline__ void ldsm_x4(uint32_t& r0, uint32_t& r1, uint32_t& r2, uint32_t& r3,
                                        uint32_t addr) {
    asm volatile("ldmatrix.sync.aligned.m8n8.x4.shared.b16 {%0,%1,%2,%3}, [%4];"
        : "=r"(r0), "=r"(r1), "=r"(r2), "=r"(r3) : "r"(addr));
}

// ======== GEMM smem layout (bytes) ========
// X split: 64 rows x 136 halves per split -> 17408B each
// W split: 128 rows x 136 halves per split -> 34816B each (hi then lo, contiguous)
#define SM_XH 0
#define SM_XL 17408
#define SM_W  34816
#define SM_GEMM_TOTAL 104448

// ============================================================
// Kernel 0: pre-split weights into ldmatrix-ready global images
// grid 32 (4 matrices x 8 row-parts), 256 threads
// ============================================================
__global__ __launch_bounds__(256) void prep_w_kernel(
    const float* __restrict__ Wq, const float* __restrict__ Wk,
    const float* __restrict__ Wv, const float* __restrict__ Wp)
{
    const float* Ws[4] = {Wq, Wk, Wv, Wp};
    const int mtx  = blockIdx.x >> 3;
    const int part = blockIdx.x & 7;
    const float* W = Ws[mtx];
    char* img = g_wimg + mtx * 69632;
    const int tid = threadIdx.x;
    const int row = part * 16 + (tid >> 4);
    const int colseg = (tid & 15) * 8;

    float4 f0 = *(const float4*)(W + row * 128 + colseg);
    float4 f1 = *(const float4*)(W + row * 128 + colseg + 4);
    uint32_t h[4], l[4];
    split_pair(f0.x, f0.y, h[0], l[0]);
    split_pair(f0.z, f0.w, h[1], l[1]);
    split_pair(f1.x, f1.y, h[2], l[2]);
    split_pair(f1.z, f1.w, h[3], l[3]);
    *(uint4*)(img + (row * 136 + colseg) * 2)         = make_uint4(h[0], h[1], h[2], h[3]);
    *(uint4*)(img + 34816 + (row * 136 + colseg) * 2) = make_uint4(l[0], l[1], l[2], l[3]);
}

// ---- shared building blocks for the projection GEMMs ----

// stage 64 rows of X (fp32, row stride 128) into split smem images
__device__ __forceinline__ void stage_x(char* smem, const float* __restrict__ Xsrc, int tid) {
    const int row = tid >> 2;
    const int seg = tid & 3;
    const float* xr = Xsrc + (size_t)row * 128 + seg * 32;
    char* dh = smem + SM_XH + (row * 136 + seg * 32) * 2;
    char* dl = smem + SM_XL + (row * 136 + seg * 32) * 2;
    #pragma unroll
    for (int i = 0; i < 4; i++) {
        float4 a = ((const float4*)xr)[2 * i];
        float4 c = ((const float4*)xr)[2 * i + 1];
        uint32_t h0, h1, h2, h3, l0, l1, l2, l3;
        split_pair(a.x, a.y, h0, l0); split_pair(a.z, a.w, h1, l1);
        split_pair(c.x, c.y, h2, l2); split_pair(c.z, c.w, h3, l3);
        *(uint4*)(dh + i * 16) = make_uint4(h0, h1, h2, h3);
        *(uint4*)(dl + i * 16) = make_uint4(l0, l1, l2, l3);
    }
}

// copy one W image (hi+lo, 69632B = 4352 uint4) into smem
__device__ __forceinline__ void copy_w(char* smem, int mtx, int tid) {
    const uint4* src = (const uint4*)(g_wimg + mtx * 69632);
    uint4* dst = (uint4*)(smem + SM_W);
    #pragma unroll
    for (int i = 0; i < 17; i++) dst[tid + i * 256] = src[tid + i * 256];
}

// per-warp 3-term split GEMM: 16 rows x 64 cols, K=128, A+B via ldmatrix
__device__ __forceinline__ void gemm_warp(uint32_t xa_h, uint32_t xa_l,
                                          uint32_t wb_h, uint32_t wb_l,
                                          int warp_n, uint32_t lda_off, uint32_t ldb_off,
                                          float acc[8][4]) {
    #pragma unroll
    for (int i = 0; i < 8; i++)
        #pragma unroll
        for (int j = 0; j < 4; j++) acc[i][j] = 0.f;

    #pragma unroll
    for (int kc = 0; kc < 8; kc++) {
        uint32_t ah[4], al[4];
        ldsm_x4(ah[0], ah[1], ah[2], ah[3], xa_h + kc * 32 + lda_off);
        ldsm_x4(al[0], al[1], al[2], al[3], xa_l + kc * 32 + lda_off);
        #pragma unroll
        for (int np = 0; np < 4; np++) {
            uint32_t roff = (uint32_t)((warp_n * 64 + np * 16) * 272 + kc * 32) + ldb_off;
            uint32_t bh0, bh1, bh2, bh3, bl0, bl1, bl2, bl3;
            ldsm_x4(bh0, bh1, bh2, bh3, wb_h + roff);
            ldsm_x4(bl0, bl1, bl2, bl3, wb_l + roff);
            mma16816(acc[2*np],   ah, bh0, bh1);
            mma16816(acc[2*np],   al, bh0, bh1);
            mma16816(acc[2*np],   ah, bl0, bl1);
            mma16816(acc[2*np+1], ah, bh2, bh3);
            mma16816(acc[2*np+1], al, bh2, bh3);
            mma16816(acc[2*np+1], ah, bl2, bl3);
        }
    }
}

// ============================================================
// Kernel 1: fused QKV projection.
// CTA = 64 rows; 8 warps (4m x 2n). Q -> g_q fp32 (scaled);
// K,V -> pre-split bf16 tile images (attention-ready layout).
// ============================================================
__global__ __launch_bounds__(256, 2) void qkv_mma_kernel(const float* __restrict__ x)
{
    extern __shared__ __align__(16) char smem[];
    const int tid  = threadIdx.x;
    const int warp = tid >> 5;
    const int lane = tid & 31;
    const int g = lane >> 2;
    const int t = lane & 3;
    const int warp_m = warp >> 1;
    const int warp_n = warp & 1;
    const int row_cta = blockIdx.x * 64;

    stage_x(smem, x + (size_t)row_cta * 128, tid);

    const uint32_t sbase = smem_to_u32(smem);
    const uint32_t xa_h = sbase + SM_XH + warp_m * 16 * 272;
    const uint32_t xa_l = sbase + SM_XL + warp_m * 16 * 272;
    const uint32_t wb_h = sbase + SM_W;
    const uint32_t wb_l = sbase + SM_W + 34816;
    const uint32_t lda_off = (uint32_t)((lane & 15) * 272 + (lane >> 4) * 16);
    const uint32_t ldb_off = (uint32_t)(((lane & 7) + ((lane >> 4) & 1) * 8) * 272
                                        + ((lane >> 3) & 1) * 16);

    const int rT = row_cta + warp_m * 16 + g;
    const int b  = rT >> 11;
    const int sT = rT & 2047;
    const int tile = (sT & 2047) >> 6;
    const int r    = sT & 63;

    for (int mtx = 0; mtx < 3; mtx++) {
        if (mtx) __syncthreads();
        copy_w(smem, mtx, tid);          // slot 0=Wq, 1=Wk, 2=Wv
        __syncthreads();

        float acc[8][4];
        gemm_warp(xa_h, xa_l, wb_h, wb_l, warp_n, lda_off, ldb_off, acc);

        if (mtx == 0) {
            #pragma unroll
            for (int nt = 0; nt < 8; nt++) {
                int col = warp_n * 64 + nt * 8 + 2 * t;
                int h = col >> 4, d = col & 15;
                float* pT = g_q + ((size_t)(b * NH + h) * S_LEN + sT) * HS + d;
                *(float2*)pT = make_float2(acc[nt][0] * QSCALE, acc[nt][1] * QSCALE);
                *(float2*)(pT + 8 * HS) = make_float2(acc[nt][2] * QSCALE, acc[nt][3] * QSCALE);
            }
        } else {
            const int imgoff = (mtx == 1) ? 0 : 6144;   // K -> blocks 0/1, V -> 2/3
            #pragma unroll
            for (int nt = 0; nt < 8; nt++) {
                int col = warp_n * 64 + nt * 8 + 2 * t;
                int h = col >> 4, d = col & 15;
                int bh = b * NH + h;
                char* base = g_kvimg + (size_t)(bh * 32 + tile) * 12288 + imgoff
                             + (r * 24 + d) * 2;
                uint32_t hi, lo;
                split_pair(acc[nt][0], acc[nt][1], hi, lo);
                *(uint32_t*)base = hi;
                *(uint32_t*)(base + 3072) = lo;
                split_pair(acc[nt][2], acc[nt][3], hi, lo);
                *(uint32_t*)(base + 384) = hi;            // row r+8 (8*48B)
                *(uint32_t*)(base + 384 + 3072) = lo;
            }
        }
    }
}

// ============================================================
// Kernel 2: FA2-style HMMA flash attention.
// CTA = (b, h, 256 queries); 8 warps x 32 queries; key tile 64.
// K/V arrive pre-split: per tile just a 12KB coalesced copy
// with register prefetch of the next tile.
// ============================================================
__global__ __launch_bounds__(256) void att_mma_kernel()
{
    __shared__ __align__(16) char sKV[12288];   // Kh | Kl | Vh | Vl (64x24 halves each)

    const int tid  = threadIdx.x;
    const int warp = tid >> 5;
    const int lane = tid & 31;
    const int g = lane >> 2;
    const int t = lane & 3;
    const int bid = blockIdx.x;
    const int qt = bid & 7;
    const int h  = (bid >> 3) & 7;
    const int b  = bid >> 6;
    const int bh = b * NH + h;
    const int qbase = qt * 256 + warp * 32;

    // ---- Q fragments (resident; 2 m-tiles, hi+lo split) ----
    uint32_t qh[2][4], ql[2][4];
    {
        const float* Qg = g_q + (size_t)bh * S_LEN * HS;
        #pragma unroll
        for (int mt = 0; mt < 2; mt++) {
            int rA = qbase + mt * 16 + g;
            int rB = rA + 8;
            float2 a0 = *(const float2*)(Qg + rA * HS + 2 * t);
            float2 a1 = *(const float2*)(Qg + rB * HS + 2 * t);
            float2 a2 = *(const float2*)(Qg + rA * HS + 2 * t + 8);
            float2 a3 = *(const float2*)(Qg + rB * HS + 2 * t + 8);
            split_pair(a0.x, a0.y, qh[mt][0], ql[mt][0]);
            split_pair(a1.x, a1.y, qh[mt][1], ql[mt][1]);
            split_pair(a2.x, a2.y, qh[mt][2], ql[mt][2]);
            split_pair(a3.x, a3.y, qh[mt][3], ql[mt][3]);
        }
    }

    float o[2][2][4];
    #pragma unroll
    for (int mt = 0; mt < 2; mt++)
        #pragma unroll
        for (int nO = 0; nO < 2; nO++)
            #pragma unroll
            for (int j = 0; j < 4; j++) o[mt][nO][j] = 0.f;
    float m[4] = {-1e30f, -1e30f, -1e30f, -1e30f};
    float l[4] = {0.f, 0.f, 0.f, 0.f};

    const uint32_t kh_b = smem_to_u32(sKV);
    const uint32_t kl_b = kh_b + 3072;
    const uint32_t vh_b = kh_b + 6144;
    const uint32_t vl_b = kh_b + 9216;
    const int l15 = lane & 15;
    const uint32_t k_off = (uint32_t)((lane & 7) * 48 + ((l15 >> 3) << 4));
    const uint32_t v_off = (uint32_t)(l15 * 48);

    const uint4* src = (const uint4*)(g_kvimg + (size_t)bh * 32 * 12288);
    uint4* dstS = (uint4*)sKV;

    uint4 pf0 = src[tid], pf1 = src[tid + 256], pf2 = src[tid + 512];

    for (int kt = 0; kt < S_LEN / 64; kt++) {
        dstS[tid] = pf0; dstS[tid + 256] = pf1; dstS[tid + 512] = pf2;
        __syncthreads();
        if (kt < S_LEN / 64 - 1) {
            const uint4* s2 = src + (kt + 1) * 768;
            pf0 = s2[tid]; pf1 = s2[tid + 256]; pf2 = s2[tid + 512];
        }

        // ---- S = Q K^T over 8 n-tiles of 8 keys (3-term split) ----
        float sc[2][8][4];
        #pragma unroll
        for (int mt = 0; mt < 2; mt++)
            #pragma unroll
            for (int n = 0; n < 8; n++)
                #pragma unroll
                for (int j = 0; j < 4; j++) sc[mt][n][j] = 0.f;

        #pragma unroll
        for (int n = 0; n < 8; n++) {
            uint32_t kh0, kh1, kl0, kl1;
            ldsm_x2(kh0, kh1, kh_b + n * 384 + k_off);
            ldsm_x2(kl0, kl1, kl_b + n * 384 + k_off);
            #pragma unroll
            for (int mt = 0; mt < 2; mt++) {
                mma16816(sc[mt][n], qh[mt], kh0, kh1);
                mma16816(sc[mt][n], ql[mt], kh0, kh1);
                mma16816(sc[mt][n], qh[mt], kl0, kl1);
            }
        }

        // ---- online softmax ----
        #pragma unroll
        for (int mt = 0; mt < 2; mt++) {
            float mxt = -1e30f, mxb = -1e30f;
            #pragma unroll
            for (int n = 0; n < 8; n++) {
                mxt = fmaxf(mxt, fmaxf(sc[mt][n][0], sc[mt][n][1]));
                mxb = fmaxf(mxb, fmaxf(sc[mt][n][2], sc[mt][n][3]));
            }
            mxt = fmaxf(mxt, __shfl_xor_sync(0xffffffffu, mxt, 1));
            mxt = fmaxf(mxt, __shfl_xor_sync(0xffffffffu, mxt, 2));
            mxb = fmaxf(mxb, __shfl_xor_sync(0xffffffffu, mxb, 1));
            mxb = fmaxf(mxb, __shfl_xor_sync(0xffffffffu, mxb, 2));

            const int st = mt * 2, sbo = mt * 2 + 1;
            float mnt = fmaxf(m[st],  mxt);
            float mnb = fmaxf(m[sbo], mxb);
            float ct = ex2f(m[st]  - mnt);
            float cb = ex2f(m[sbo] - mnb);
            m[st] = mnt; m[sbo] = mnb;
            l[st] *= ct; l[sbo] *= cb;
            #pragma unroll
            for (int nO = 0; nO < 2; nO++) {
                o[mt][nO][0] *= ct; o[mt][nO][1] *= ct;
                o[mt][nO][2] *= cb; o[mt][nO][3] *= cb;
            }
            float lt = 0.f, lb = 0.f;
            #pragma unroll
            for (int n = 0; n < 8; n++) {
                sc[mt][n][0] = ex2f(sc[mt][n][0] - mnt);
                sc[mt][n][1] = ex2f(sc[mt][n][1] - mnt);
                sc[mt][n][2] = ex2f(sc[mt][n][2] - mnb);
                sc[mt][n][3] = ex2f(sc[mt][n][3] - mnb);
                lt += sc[mt][n][0] + sc[mt][n][1];
                lb += sc[mt][n][2] + sc[mt][n][3];
            }
            l[st] += lt; l[sbo] += lb;
        }

        // ---- O += P V  (P from regs; V hi+lo via trans ldmatrix) ----
        #pragma unroll
        for (int ks = 0; ks < 4; ks++) {
            uint32_t pa[2][4];
            #pragma unroll
            for (int mt = 0; mt < 2; mt++) {
                CVT_BF16X2_F32(pa[mt][0], sc[mt][2*ks  ][0], sc[mt][2*ks  ][1]);
                CVT_BF16X2_F32(pa[mt][1], sc[mt][2*ks  ][2], sc[mt][2*ks  ][3]);
                CVT_BF16X2_F32(pa[mt][2], sc[mt][2*ks+1][0], sc[mt][2*ks+1][1]);
                CVT_BF16X2_F32(pa[mt][3], sc[mt][2*ks+1][2], sc[mt][2*ks+1][3]);
            }
            #pragma unroll
            for (int nO = 0; nO < 2; nO++) {
                uint32_t vh0, vh1, vl0, vl1;
                ldsm_x2_t(vh0, vh1, vh_b + ks * 768 + v_off + nO * 16);
                ldsm_x2_t(vl0, vl1, vl_b + ks * 768 + v_off + nO * 16);
                mma16816(o[0][nO], pa[0], vh0, vh1);
                mma16816(o[0][nO], pa[0], vl0, vl1);
                mma16816(o[1][nO], pa[1], vh0, vh1);
                mma16816(o[1][nO], pa[1], vl0, vl1);
            }
        }
        __syncthreads();
    }

    // ---- epilogue ----
    #pragma unroll
    for (int s = 0; s < 4; s++) {
        l[s] += __shfl_xor_sync(0xffffffffu, l[s], 1);
        l[s] += __shfl_xor_sync(0xffffffffu, l[s], 2);
    }
    #pragma unroll
    for (int mt = 0; mt < 2; mt++) {
        int rT = qbase + mt * 16 + g;
        int rB = rT + 8;
        float iT = 1.0f / l[mt * 2];
        float iB = 1.0f / l[mt * 2 + 1];
        #pragma unroll
        for (int nO = 0; nO < 2; nO++) {
            float* pT = g_ocat + ((size_t)b * S_LEN + rT) * E_SZ + h * HS + nO * 8 + 2 * t;
            float* pB = g_ocat + ((size_t)b * S_LEN + rB) * E_SZ + h * HS + nO * 8 + 2 * t;
            *(float2*)pT = make_float2(o[mt][nO][0] * iT, o[mt][nO][1] * iT);
            *(float2*)pB = make_float2(o[mt][nO][2] * iB, o[mt][nO][3] * iB);
        }
    }
}

// ============================================================
// Kernel 3: output projection  out = ocat @ Wp^T + bp
// ============================================================
__global__ __launch_bounds__(256, 2) void proj_mma_kernel(
    const float* __restrict__ bp,
    float* __restrict__ out)
{
    extern __shared__ __align__(16) char smem[];
    const int tid  = threadIdx.x;
    const int warp = tid >> 5;
    const int lane = tid & 31;
    const int g = lane >> 2;
    const int t = lane & 3;
    const int warp_m = warp >> 1;
    const int warp_n = warp & 1;
    const int row_cta = blockIdx.x * 64;

    stage_x(smem, g_ocat + (size_t)row_cta * 128, tid);
    copy_w(smem, 3, tid);                      // Wp image
    __syncthreads();

    const uint32_t sbase = smem_to_u32(smem);
    const uint32_t xa_h = sbase + SM_XH + warp_m * 16 * 272;
    const uint32_t xa_l = sbase + SM_XL + warp_m * 16 * 272;
    const uint32_t wb_h = sbase + SM_W;
    const uint32_t wb_l = sbase + SM_W + 34816;
    const uint32_t lda_off = (uint32_t)((lane & 15) * 272 + (lane >> 4) * 16);
    const uint32_t ldb_off = (uint32_t)(((lane & 7) + ((lane >> 4) & 1) * 8) * 272
                                        + ((lane >> 3) & 1) * 16);

    float acc[8][4];
    gemm_warp(xa_h, xa_l, wb_h, wb_l, warp_n, lda_off, ldb_off, acc);

    const int rT = row_cta + warp_m * 16 + g;
    #pragma unroll
    for (int nt = 0; nt < 8; nt++) {
        int col = warp_n * 64 + nt * 8 + 2 * t;
        float2 bias = *(const float2*)(bp + col);
        float* pT = out + (size_t)rT * 128 + col;
        *(float2*)pT = make_float2(acc[nt][0] + bias.x, acc[nt][1] + bias.y);
        *(float2*)(pT + 8 * 128) = make_float2(acc[nt][2] + bias.x, acc[nt][3] + bias.y);
    }
}

// ============================================================
// launch: inputs are (x, Wk, Wq, Wv, Wp, bp) per metadata order
// ============================================================
extern "C" void kernel_launch(void* const* d_in, const int* in_sizes, int n_in,
                              void* d_out, int out_size)
{
    const float* x  = (const float*)d_in[0];
    const float* Wk = (const float*)d_in[1];
    const float* Wq = (const float*)d_in[2];
    const float* Wv = (const float*)d_in[3];
    const float* Wp = (const float*)d_in[4];
    const float* bp = (const float*)d_in[5];
    float* out = (float*)d_out;

    cudaFuncSetAttribute(qkv_mma_kernel,  cudaFuncAttributeMaxDynamicSharedMemorySize, SM_GEMM_TOTAL);
    cudaFuncSetAttribute(proj_mma_kernel, cudaFuncAttributeMaxDynamicSharedMemorySize, SM_GEMM_TOTAL);

    prep_w_kernel<<<32, 256>>>(Wq, Wk, Wv, Wp);
    qkv_mma_kernel<<<ROWS_TOTAL / 64, 256, SM_GEMM_TOTAL>>>(x);
    att_mma_kernel<<<B_SZ * NH * (S_LEN / 256), 256>>>();
    proj_mma_kernel<<<ROWS_TOTAL / 64, 256, SM_GEMM_TOTAL>>>(bp, out);
}

// round 12
// speedup vs baseline: 1.4663x; 1.0391x over previous
#include <cuda_runtime.h>
#include <cstdint>

// Shapes (fixed for this problem)
#define B_SZ   8
#define S_LEN  2048
#define E_SZ   128
#define NH     8
#define HS     16
#define ROWS_TOTAL (B_SZ * S_LEN)          // 16384

// softmax in base-2: fold scale = sqrt(hs)*log2(e) into Q
#define QSCALE 5.7707801635558535f          // 4 * log2(e)

// -------- scratch (device globals; no allocation allowed) --------
__device__ float g_q[B_SZ * NH * S_LEN * HS];              // [b,h,s,d] (pre-scaled)
__device__ float g_ocat[ROWS_TOTAL * E_SZ];                // [b*s, h*hs]
// W images: 4 matrices x (hi 34816B + lo 34816B), 136-half row stride
__device__ __align__(16) char g_wimg[4 * 69632];
// K/V tile images: [bh][tile] x 12288B block = Kh(64x24h) | Kl | Vh | Vl
#define KVBLK 12288
__device__ __align__(16) char g_kvimg[B_SZ * NH * 32 * KVBLK];

// ================= helpers =================
__device__ __forceinline__ float ex2f(float x) {
    float y; asm("ex2.approx.ftz.f32 %0, %1;" : "=f"(y) : "f"(x)); return y;
}
__device__ __forceinline__ uint32_t smem_to_u32(const void* p) {
    uint32_t a;
    asm("{ .reg .u64 t; cvta.to.shared.u64 t, %1; cvt.u32.u64 %0, t; }" : "=r"(a) : "l"(p));
    return a;
}
#define CVT_BF16X2_F32(result, a, b) \
    asm("cvt.rn.satfinite.bf16x2.f32 %0, %1, %2;" : "=r"(result) : "f"(b), "f"(a))

__device__ __forceinline__ void split_pair(float a, float c, uint32_t& hi, uint32_t& lo) {
    CVT_BF16X2_F32(hi, a, c);
    float ar = a - __uint_as_float(hi << 16);
    float cr = c - __uint_as_float(hi & 0xffff0000u);
    CVT_BF16X2_F32(lo, ar, cr);
}

__device__ __forceinline__ void mma16816(float* c, const uint32_t* a, uint32_t b0, uint32_t b1) {
    asm volatile("mma.sync.aligned.m16n8k16.row.col.f32.bf16.bf16.f32 "
        "{%0,%1,%2,%3}, {%4,%5,%6,%7}, {%8,%9}, {%0,%1,%2,%3};"
        : "+f"(c[0]), "+f"(c[1]), "+f"(c[2]), "+f"(c[3])
        : "r"(a[0]), "r"(a[1]), "r"(a[2]), "r"(a[3]), "r"(b0), "r"(b1));
}
__device__ __forceinline__ void ldsm_x4(uint32_t& r0, uint32_t& r1, uint32_t& r2, uint32_t& r3,
                                        uint32_t addr) {
    asm volatile("ldmatrix.sync.aligned.m8n8.x4.shared.b16 {%0,%1,%2,%3}, [%4];"
        : "=r"(r0), "=r"(r1), "=r"(r2), "=r"(r3) : "r"(addr));
}
__device__ __forceinline__ void ldsm_x4_t(uint32_t& r0, uint32_t& r1, uint32_t& r2, uint32_t& r3,
                                          uint32_t addr) {
    asm volatile("ldmatrix.sync.aligned.m8n8.x4.trans.shared.b16 {%0,%1,%2,%3}, [%4];"
        : "=r"(r0), "=r"(r1), "=r"(r2), "=r"(r3) : "r"(addr));
}

// ======== GEMM smem layout (bytes) ========
#define SM_XH 0
#define SM_XL 17408
#define SM_W  34816                      // W hi|lo (69632B); reused as K/V staging
#define SM_GEMM_TOTAL 104448

// ============================================================
// Kernel 0: pre-split weights into ldmatrix-ready global images
// ============================================================
__global__ __launch_bounds__(256) void prep_w_kernel(
    const float* __restrict__ Wq, const float* __restrict__ Wk,
    const float* __restrict__ Wv, const float* __restrict__ Wp)
{
    const float* Ws[4] = {Wq, Wk, Wv, Wp};
    const int mtx  = blockIdx.x >> 3;
    const int part = blockIdx.x & 7;
    const float* W = Ws[mtx];
    char* img = g_wimg + mtx * 69632;
    const int tid = threadIdx.x;
    const int row = part * 16 + (tid >> 4);
    const int colseg = (tid & 15) * 8;

    float4 f0 = *(const float4*)(W + row * 128 + colseg);
    float4 f1 = *(const float4*)(W + row * 128 + colseg + 4);
    uint32_t h[4], l[4];
    split_pair(f0.x, f0.y, h[0], l[0]);
    split_pair(f0.z, f0.w, h[1], l[1]);
    split_pair(f1.x, f1.y, h[2], l[2]);
    split_pair(f1.z, f1.w, h[3], l[3]);
    *(uint4*)(img + (row * 136 + colseg) * 2)         = make_uint4(h[0], h[1], h[2], h[3]);
    *(uint4*)(img + 34816 + (row * 136 + colseg) * 2) = make_uint4(l[0], l[1], l[2], l[3]);
}

// ---- shared building blocks for the projection GEMMs ----
__device__ __forceinline__ void stage_x(char* smem, const float* __restrict__ Xsrc, int tid) {
    const int row = tid >> 2;
    const int seg = tid & 3;
    const float* xr = Xsrc + (size_t)row * 128 + seg * 32;
    char* dh = smem + SM_XH + (row * 136 + seg * 32) * 2;
    char* dl = smem + SM_XL + (row * 136 + seg * 32) * 2;
    #pragma unroll
    for (int i = 0; i < 4; i++) {
        float4 a = ((const float4*)xr)[2 * i];
        float4 c = ((const float4*)xr)[2 * i + 1];
        uint32_t h0, h1, h2, h3, l0, l1, l2, l3;
        split_pair(a.x, a.y, h0, l0); split_pair(a.z, a.w, h1, l1);
        split_pair(c.x, c.y, h2, l2); split_pair(c.z, c.w, h3, l3);
        *(uint4*)(dh + i * 16) = make_uint4(h0, h1, h2, h3);
        *(uint4*)(dl + i * 16) = make_uint4(l0, l1, l2, l3);
    }
}

__device__ __forceinline__ void copy_w(char* smem, int mtx, int tid) {
    const uint4* src = (const uint4*)(g_wimg + mtx * 69632);
    uint4* dst = (uint4*)(smem + SM_W);
    #pragma unroll
    for (int i = 0; i < 17; i++) dst[tid + i * 256] = src[tid + i * 256];
}

__device__ __forceinline__ void gemm_warp(uint32_t xa_h, uint32_t xa_l,
                                          uint32_t wb_h, uint32_t wb_l,
                                          int warp_n, uint32_t lda_off, uint32_t ldb_off,
                                          float acc[8][4]) {
    #pragma unroll
    for (int i = 0; i < 8; i++)
        #pragma unroll
        for (int j = 0; j < 4; j++) acc[i][j] = 0.f;

    #pragma unroll
    for (int kc = 0; kc < 8; kc++) {
        uint32_t ah[4], al[4];
        ldsm_x4(ah[0], ah[1], ah[2], ah[3], xa_h + kc * 32 + lda_off);
        ldsm_x4(al[0], al[1], al[2], al[3], xa_l + kc * 32 + lda_off);
        #pragma unroll
        for (int np = 0; np < 4; np++) {
            uint32_t roff = (uint32_t)((warp_n * 64 + np * 16) * 272 + kc * 32) + ldb_off;
            uint32_t bh0, bh1, bh2, bh3, bl0, bl1, bl2, bl3;
            ldsm_x4(bh0, bh1, bh2, bh3, wb_h + roff);
            ldsm_x4(bl0, bl1, bl2, bl3, wb_l + roff);
            mma16816(acc[2*np],   ah, bh0, bh1);
            mma16816(acc[2*np],   al, bh0, bh1);
            mma16816(acc[2*np],   ah, bl0, bl1);
            mma16816(acc[2*np+1], ah, bh2, bh3);
            mma16816(acc[2*np+1], al, bh2, bh3);
            mma16816(acc[2*np+1], ah, bl2, bl3);
        }
    }
}

// ============================================================
// Kernel 1: fused QKV projection.
// Q -> g_q fp32 (scaled). K,V -> split bf16 tile images via
// smem staging + fully coalesced stores.
// ============================================================
__global__ __launch_bounds__(256, 2) void qkv_mma_kernel(const float* __restrict__ x)
{
    extern __shared__ __align__(16) char smem[];
    const int tid  = threadIdx.x;
    const int warp = tid >> 5;
    const int lane = tid & 31;
    const int g = lane >> 2;
    const int t = lane & 3;
    const int warp_m = warp >> 1;
    const int warp_n = warp & 1;
    const int row_cta = blockIdx.x * 64;

    stage_x(smem, x + (size_t)row_cta * 128, tid);

    const uint32_t sbase = smem_to_u32(smem);
    const uint32_t xa_h = sbase + SM_XH + warp_m * 16 * 272;
    const uint32_t xa_l = sbase + SM_XL + warp_m * 16 * 272;
    const uint32_t wb_h = sbase + SM_W;
    const uint32_t wb_l = sbase + SM_W + 34816;
    const uint32_t lda_off = (uint32_t)((lane & 15) * 272 + (lane >> 4) * 16);
    const uint32_t ldb_off = (uint32_t)(((lane & 7) + ((lane >> 4) & 1) * 8) * 272
                                        + ((lane >> 3) & 1) * 16);

    const int rT = row_cta + warp_m * 16 + g;
    const int b_cta = row_cta >> 11;
    const int sT = rT & 2047;
    const int tile = (row_cta & 2047) >> 6;   // constant per CTA
    const int r = warp_m * 16 + g;            // local row 0..63

    for (int mtx = 0; mtx < 3; mtx++) {
        if (mtx) __syncthreads();
        copy_w(smem, mtx, tid);               // 0=Wq, 1=Wk, 2=Wv
        __syncthreads();

        float acc[8][4];
        gemm_warp(xa_h, xa_l, wb_h, wb_l, warp_n, lda_off, ldb_off, acc);

        if (mtx == 0) {
            #pragma unroll
            for (int nt = 0; nt < 8; nt++) {
                int col = warp_n * 64 + nt * 8 + 2 * t;
                int h = col >> 4, d = col & 15;
                float* pT = g_q + ((size_t)(b_cta * NH + h) * S_LEN + sT) * HS + d;
                *(float2*)pT = make_float2(acc[nt][0] * QSCALE, acc[nt][1] * QSCALE);
                *(float2*)(pT + 8 * HS) = make_float2(acc[nt][2] * QSCALE, acc[nt][3] * QSCALE);
            }
        } else {
            // ---- K or V: stage hi+lo per head in smem, then coalesced store ----
            const int imgoff = (mtx == 1) ? 0 : 6144;   // K -> 0/3072, V -> 6144/9216
            __syncthreads();                  // gemm reads of W done in all warps
            #pragma unroll
            for (int nt = 0; nt < 8; nt++) {
                int col = warp_n * 64 + nt * 8 + 2 * t;
                int hh = col >> 4, d = col & 15;
                char* st = smem + SM_W + hh * 6144 + (r * 24 + d) * 2;
                uint32_t hi, lo;
                split_pair(acc[nt][0], acc[nt][1], hi, lo);
                *(uint32_t*)st = hi;  *(uint32_t*)(st + 3072) = lo;
                split_pair(acc[nt][2], acc[nt][3], hi, lo);
                *(uint32_t*)(st + 384) = hi;  *(uint32_t*)(st + 384 + 3072) = lo;
            }
            __syncthreads();
            const uint4* src = (const uint4*)(smem + SM_W);
            #pragma unroll
            for (int i = 0; i < 12; i++) {
                int idx = tid + i * 256;          // uint4 units, 0..3071
                int hh = idx / 384;               // 6144B per head
                int off = idx - hh * 384;
                uint4* dst = (uint4*)(g_kvimg
                    + ((size_t)(b_cta * NH + hh) * 32 + tile) * KVBLK + imgoff) + off;
                *dst = src[idx];
            }
        }
    }
}

// ============================================================
// Kernel 2: FA2-style HMMA flash attention.
// CTA = (b, h, 256 queries); 8 warps x 32 queries; key tile 64.
// Per tile: 12KB coalesced copy (prefetched), x4 ldsm, 80 MMAs/warp.
// ============================================================
__global__ __launch_bounds__(256, 2) void att_mma_kernel()
{
    __shared__ __align__(16) char sKV[KVBLK];   // Kh | Kl | Vh | Vl (64x24 halves each)

    const int tid  = threadIdx.x;
    const int warp = tid >> 5;
    const int lane = tid & 31;
    const int g = lane >> 2;
    const int t = lane & 3;
    const int bid = blockIdx.x;
    const int qt = bid & 7;
    const int h  = (bid >> 3) & 7;
    const int b  = bid >> 6;
    const int bh = b * NH + h;
    const int qbase = qt * 256 + warp * 32;

    uint32_t qh[2][4], ql[2][4];
    {
        const float* Qg = g_q + (size_t)bh * S_LEN * HS;
        #pragma unroll
        for (int mt = 0; mt < 2; mt++) {
            int rA = qbase + mt * 16 + g;
            int rB = rA + 8;
            float2 a0 = *(const float2*)(Qg + rA * HS + 2 * t);
            float2 a1 = *(const float2*)(Qg + rB * HS + 2 * t);
            float2 a2 = *(const float2*)(Qg + rA * HS + 2 * t + 8);
            float2 a3 = *(const float2*)(Qg + rB * HS + 2 * t + 8);
            split_pair(a0.x, a0.y, qh[mt][0], ql[mt][0]);
            split_pair(a1.x, a1.y, qh[mt][1], ql[mt][1]);
            split_pair(a2.x, a2.y, qh[mt][2], ql[mt][2]);
            split_pair(a3.x, a3.y, qh[mt][3], ql[mt][3]);
        }
    }

    float o[2][2][4];
    #pragma unroll
    for (int mt = 0; mt < 2; mt++)
        #pragma unroll
        for (int nO = 0; nO < 2; nO++)
            #pragma unroll
            for (int j = 0; j < 4; j++) o[mt][nO][j] = 0.f;
    float m[4] = {-1e30f, -1e30f, -1e30f, -1e30f};
    float l[4] = {0.f, 0.f, 0.f, 0.f};

    const uint32_t kh_b = smem_to_u32(sKV);
    const uint32_t kl_b = kh_b + 3072;
    const uint32_t vh_b = kh_b + 6144;
    const uint32_t vl_b = kh_b + 9216;
    const uint32_t k4_off = (uint32_t)(((lane & 7) + ((lane >> 4) & 1) * 8) * 48
                                       + ((lane >> 3) & 1) * 16);
    const uint32_t v4_off = (uint32_t)((lane & 15) * 48 + (lane >> 4) * 16);

    const uint4* src = (const uint4*)(g_kvimg + (size_t)bh * 32 * KVBLK);
    uint4* dstS = (uint4*)sKV;

    uint4 pf0 = src[tid], pf1 = src[tid + 256], pf2 = src[tid + 512];

    for (int kt = 0; kt < S_LEN / 64; kt++) {
        dstS[tid] = pf0; dstS[tid + 256] = pf1; dstS[tid + 512] = pf2;
        __syncthreads();
        if (kt < S_LEN / 64 - 1) {
            const uint4* s2 = src + (kt + 1) * (KVBLK / 16);
            pf0 = s2[tid]; pf1 = s2[tid + 256]; pf2 = s2[tid + 512];
        }

        // ---- S = Q K^T (3-term split), x4 ldsm over pairs of n-tiles ----
        float sc[2][8][4];
        #pragma unroll
        for (int mt = 0; mt < 2; mt++)
            #pragma unroll
            for (int n = 0; n < 8; n++)
                #pragma unroll
                for (int j = 0; j < 4; j++) sc[mt][n][j] = 0.f;

        #pragma unroll
        for (int n2 = 0; n2 < 4; n2++) {
            uint32_t kh0, kh1, kh2, kh3, kl0, kl1, kl2, kl3;
            ldsm_x4(kh0, kh1, kh2, kh3, kh_b + n2 * 768 + k4_off);
            ldsm_x4(kl0, kl1, kl2, kl3, kl_b + n2 * 768 + k4_off);
            #pragma unroll
            for (int mt = 0; mt < 2; mt++) {
                mma16816(sc[mt][2*n2],   qh[mt], kh0, kh1);
                mma16816(sc[mt][2*n2],   ql[mt], kh0, kh1);
                mma16816(sc[mt][2*n2],   qh[mt], kl0, kl1);
                mma16816(sc[mt][2*n2+1], qh[mt], kh2, kh3);
                mma16816(sc[mt][2*n2+1], ql[mt], kh2, kh3);
                mma16816(sc[mt][2*n2+1], qh[mt], kl2, kl3);
            }
        }

        // ---- online softmax ----
        #pragma unroll
        for (int mt = 0; mt < 2; mt++) {
            float mxt = -1e30f, mxb = -1e30f;
            #pragma unroll
            for (int n = 0; n < 8; n++) {
                mxt = fmaxf(mxt, fmaxf(sc[mt][n][0], sc[mt][n][1]));
                mxb = fmaxf(mxb, fmaxf(sc[mt][n][2], sc[mt][n][3]));
            }
            mxt = fmaxf(mxt, __shfl_xor_sync(0xffffffffu, mxt, 1));
            mxt = fmaxf(mxt, __shfl_xor_sync(0xffffffffu, mxt, 2));
            mxb = fmaxf(mxb, __shfl_xor_sync(0xffffffffu, mxb, 1));
            mxb = fmaxf(mxb, __shfl_xor_sync(0xffffffffu, mxb, 2));

            const int st = mt * 2, sbo = mt * 2 + 1;
            float mnt = fmaxf(m[st],  mxt);
            float mnb = fmaxf(m[sbo], mxb);
            float ct = ex2f(m[st]  - mnt);
            float cb = ex2f(m[sbo] - mnb);
            m[st] = mnt; m[sbo] = mnb;
            l[st] *= ct; l[sbo] *= cb;
            #pragma unroll
            for (int nO = 0; nO < 2; nO++) {
                o[mt][nO][0] *= ct; o[mt][nO][1] *= ct;
                o[mt][nO][2] *= cb; o[mt][nO][3] *= cb;
            }
            float lt = 0.f, lb = 0.f;
            #pragma unroll
            for (int n = 0; n < 8; n++) {
                sc[mt][n][0] = ex2f(sc[mt][n][0] - mnt);
                sc[mt][n][1] = ex2f(sc[mt][n][1] - mnt);
                sc[mt][n][2] = ex2f(sc[mt][n][2] - mnb);
                sc[mt][n][3] = ex2f(sc[mt][n][3] - mnb);
                lt += sc[mt][n][0] + sc[mt][n][1];
                lb += sc[mt][n][2] + sc[mt][n][3];
            }
            l[st] += lt; l[sbo] += lb;
        }

        // ---- O += P (Vh + Vl)  (x4 trans ldsm covers both nO halves) ----
        #pragma unroll
        for (int ks = 0; ks < 4; ks++) {
            uint32_t pa[2][4];
            #pragma unroll
            for (int mt = 0; mt < 2; mt++) {
                CVT_BF16X2_F32(pa[mt][0], sc[mt][2*ks  ][0], sc[mt][2*ks  ][1]);
                CVT_BF16X2_F32(pa[mt][1], sc[mt][2*ks  ][2], sc[mt][2*ks  ][3]);
                CVT_BF16X2_F32(pa[mt][2], sc[mt][2*ks+1][0], sc[mt][2*ks+1][1]);
                CVT_BF16X2_F32(pa[mt][3], sc[mt][2*ks+1][2], sc[mt][2*ks+1][3]);
            }
            uint32_t v0, v1, v2, v3, w0, w1, w2, w3;
            ldsm_x4_t(v0, v1, v2, v3, vh_b + ks * 768 + v4_off);
            ldsm_x4_t(w0, w1, w2, w3, vl_b + ks * 768 + v4_off);
            mma16816(o[0][0], pa[0], v0, v1);
            mma16816(o[0][0], pa[0], w0, w1);
            mma16816(o[1][0], pa[1], v0, v1);
            mma16816(o[1][0], pa[1], w0, w1);
            mma16816(o[0][1], pa[0], v2, v3);
            mma16816(o[0][1], pa[0], w2, w3);
            mma16816(o[1][1], pa[1], v2, v3);
            mma16816(o[1][1], pa[1], w2, w3);
        }
        __syncthreads();
    }

    // ---- epilogue ----
    #pragma unroll
    for (int s = 0; s < 4; s++) {
        l[s] += __shfl_xor_sync(0xffffffffu, l[s], 1);
        l[s] += __shfl_xor_sync(0xffffffffu, l[s], 2);
    }
    #pragma unroll
    for (int mt = 0; mt < 2; mt++) {
        int rT = qbase + mt * 16 + g;
        int rB = rT + 8;
        float iT = 1.0f / l[mt * 2];
        float iB = 1.0f / l[mt * 2 + 1];
        #pragma unroll
        for (int nO = 0; nO < 2; nO++) {
            float* pT = g_ocat + ((size_t)b * S_LEN + rT) * E_SZ + h * HS + nO * 8 + 2 * t;
            float* pB = g_ocat + ((size_t)b * S_LEN + rB) * E_SZ + h * HS + nO * 8 + 2 * t;
            *(float2*)pT = make_float2(o[mt][nO][0] * iT, o[mt][nO][1] * iT);
            *(float2*)pB = make_float2(o[mt][nO][2] * iB, o[mt][nO][3] * iB);
        }
    }
}

// ============================================================
// Kernel 3: output projection  out = ocat @ Wp^T + bp
// ============================================================
__global__ __launch_bounds__(256, 2) void proj_mma_kernel(
    const float* __restrict__ bp,
    float* __restrict__ out)
{
    extern __shared__ __align__(16) char smem[];
    const int tid  = threadIdx.x;
    const int warp = tid >> 5;
    const int lane = tid & 31;
    const int g = lane >> 2;
    const int t = lane & 3;
    const int warp_m = warp >> 1;
    const int warp_n = warp & 1;
    const int row_cta = blockIdx.x * 64;

    stage_x(smem, g_ocat + (size_t)row_cta * 128, tid);
    copy_w(smem, 3, tid);                      // Wp image
    __syncthreads();

    const uint32_t sbase = smem_to_u32(smem);
    const uint32_t xa_h = sbase + SM_XH + warp_m * 16 * 272;
    const uint32_t xa_l = sbase + SM_XL + warp_m * 16 * 272;
    const uint32_t wb_h = sbase + SM_W;
    const uint32_t wb_l = sbase + SM_W + 34816;
    const uint32_t lda_off = (uint32_t)((lane & 15) * 272 + (lane >> 4) * 16);
    const uint32_t ldb_off = (uint32_t)(((lane & 7) + ((lane >> 4) & 1) * 8) * 272
                                        + ((lane >> 3) & 1) * 16);

    float acc[8][4];
    gemm_warp(xa_h, xa_l, wb_h, wb_l, warp_n, lda_off, ldb_off, acc);

    const int rT = row_cta + warp_m * 16 + g;
    #pragma unroll
    for (int nt = 0; nt < 8; nt++) {
        int col = warp_n * 64 + nt * 8 + 2 * t;
        float2 bias = *(const float2*)(bp + col);
        float* pT = out + (size_t)rT * 128 + col;
        *(float2*)pT = make_float2(acc[nt][0] + bias.x, acc[nt][1] + bias.y);
        *(float2*)(pT + 8 * 128) = make_float2(acc[nt][2] + bias.x, acc[nt][3] + bias.y);
    }
}

// ============================================================
// launch: inputs are (x, Wk, Wq, Wv, Wp, bp) per metadata order
// ============================================================
extern "C" void kernel_launch(void* const* d_in, const int* in_sizes, int n_in,
                              void* d_out, int out_size)
{
    const float* x  = (const float*)d_in[0];
    const float* Wk = (const float*)d_in[1];
    const float* Wq = (const float*)d_in[2];
    const float* Wv = (const float*)d_in[3];
    const float* Wp = (const float*)d_in[4];
    const float* bp = (const float*)d_in[5];
    float* out = (float*)d_out;

    cudaFuncSetAttribute(qkv_mma_kernel,  cudaFuncAttributeMaxDynamicSharedMemorySize, SM_GEMM_TOTAL);
    cudaFuncSetAttribute(proj_mma_kernel, cudaFuncAttributeMaxDynamicSharedMemorySize, SM_GEMM_TOTAL);

    prep_w_kernel<<<32, 256>>>(Wq, Wk, Wv, Wp);
    qkv_mma_kernel<<<ROWS_TOTAL / 64, 256, SM_GEMM_TOTAL>>>(x);
    att_mma_kernel<<<B_SZ * NH * (S_LEN / 256), 256>>>();
    proj_mma_kernel<<<ROWS_TOTAL / 64, 256, SM_GEMM_TOTAL>>>(bp, out);
}